// round 4
// baseline (speedup 1.0000x reference)
#include <cuda_runtime.h>
#include <cuda_bf16.h>
#include <math.h>
#include <stdint.h>

#define N_NODES 65536
#define B_G     128
#define N_PG    512
#define N_E     1048576
#define K_SEL   256
#define EPG     8192

// ---------------- scratch ----------------
__device__ int   g_deg[N_NODES];
__device__ int   g_off[N_NODES];
__device__ float g_dis[N_NODES];
__device__ int   g_csr[N_E];            // graph-LOCAL source indices
__device__ float g_xw[(size_t)N_NODES * 128];
__device__ float g_h[(size_t)N_NODES * 384];
__device__ __nv_bfloat16 g_ahi[(size_t)N_NODES * 128];   // GEMM A input, hi plane
__device__ __nv_bfloat16 g_alo[(size_t)N_NODES * 128];   // GEMM A input, lo plane
__device__ float g_read[B_G * 768];
__device__ float g_z1[B_G * 256];
__device__ float g_z2[B_G * 128];

// ---------------- fused preprocessing: one block per graph ----------------
__global__ void k_prep(const int* __restrict__ src, const int* __restrict__ dst) {
    __shared__ int degs[N_PG];
    __shared__ int curs[N_PG];
    __shared__ int csr[EPG];
    int g = blockIdx.x, t = threadIdx.x;     // 512 threads
    int nb = g * N_PG, eb = g * EPG;

    degs[t] = 0;
    __syncthreads();
    for (int e = t; e < EPG; e += N_PG) atomicAdd(&degs[dst[eb + e] - nb], 1);
    __syncthreads();

    int d = degs[t];
    curs[t] = d;
    __syncthreads();
    for (int off = 1; off < N_PG; off <<= 1) {
        int v = (t >= off) ? curs[t - off] : 0;
        __syncthreads();
        curs[t] += v;
        __syncthreads();
    }
    int excl = curs[t] - d;
    g_off[nb + t] = eb + excl;
    g_deg[nb + t] = d;
    g_dis[nb + t] = rsqrtf((float)(d + 1));
    curs[t] = excl;
    __syncthreads();

    for (int e = t; e < EPG; e += N_PG) {
        int dl = dst[eb + e] - nb;
        int p = atomicAdd(&curs[dl], 1);
        csr[p] = src[eb + e] - nb;           // local src
    }
    __syncthreads();
    for (int e = t; e < EPG; e += N_PG) g_csr[eb + e] = csr[e];
}

// ---------------- split helpers ----------------
__device__ __forceinline__ void split_pack(float x, float y, uint32_t& hi, uint32_t& lo) {
    __nv_bfloat16 hx = __float2bfloat16_rn(x);
    __nv_bfloat16 hy = __float2bfloat16_rn(y);
    __nv_bfloat16 lx = __float2bfloat16_rn(x - __bfloat162float(hx));
    __nv_bfloat16 ly = __float2bfloat16_rn(y - __bfloat162float(hy));
    hi = ((uint32_t)*(uint16_t*)&hy << 16) | *(uint16_t*)&hx;
    lo = ((uint32_t)*(uint16_t*)&ly << 16) | *(uint16_t*)&lx;
}
__device__ __forceinline__ uint32_t smem_u32(const void* p) {
    return (uint32_t)__cvta_generic_to_shared(p);
}

// ---------------- x -> bf16 hi/lo planes ----------------
__global__ void k_xconv(const float* __restrict__ x) {
    size_t i = (size_t)blockIdx.x * 256 + threadIdx.x;   // float4 index
    float4 v = ((const float4*)x)[i];
    uint32_t h0, l0, h1, l1;
    split_pack(v.x, v.y, h0, l0);
    split_pack(v.z, v.w, h1, l1);
    *(uint2*)((uint16_t*)g_ahi + i * 4) = make_uint2(h0, h1);
    *(uint2*)((uint16_t*)g_alo + i * 4) = make_uint2(l0, l1);
}

// ---------------- tensor-core GEMM (bf16x3): xw[M,128] = planes(A)[M,128] @ W[128,128] ----------------
// grid (2, M/128), 256 threads, block tile 128x64, 2 CTA/SM.
// smem: sW hi/lo [128][72] u16 (36864B), sA 2buf x hi/lo x [128][56] u16 (57344B)
#define GW_STRIDE 72
#define GA_STRIDE 56
#define GA_PLANE  (128 * GA_STRIDE)
#define GA_BUF    (2 * GA_PLANE)
#define GEMM_SMEM ((2 * 128 * GW_STRIDE + 2 * GA_BUF) * 2)

__global__ void __launch_bounds__(256, 2)
k_gemm_tc(const float* __restrict__ W, float* __restrict__ C) {
    extern __shared__ uint16_t smg[];
    uint16_t* sW = smg;                        // 2 planes x 128 x 72
    uint16_t* sA = smg + 2 * 128 * GW_STRIDE;  // 2 bufs x 2 planes x 128 x 56

    int t = threadIdx.x;
    int cb = blockIdx.x * 64;
    int m0 = blockIdx.y * 128;
    int wid = t >> 5, lane = t & 31;
    int wm = (wid & 3) * 32, wn = (wid >> 2) * 32;

    // ---- convert W[:, cb:cb+64] into sW hi/lo ----
    for (int idx = t; idx < 128 * 16; idx += 256) {
        int k = idx >> 4, cq = (idx & 15) * 4;
        float4 v = *(const float4*)(W + k * 128 + cb + cq);
        uint32_t h0, l0, h1, l1;
        split_pack(v.x, v.y, h0, l0);
        split_pack(v.z, v.w, h1, l1);
        *(uint2*)(sW + k * GW_STRIDE + cq) = make_uint2(h0, h1);
        *(uint2*)(sW + 128 * GW_STRIDE + k * GW_STRIDE + cq) = make_uint2(l0, l1);
    }

    // ---- preload chunk 0 (2x 16B per plane per thread) ----
    const uint16_t* phi = (const uint16_t*)g_ahi;
    const uint16_t* plo = (const uint16_t*)g_alo;
    uint4 rh[2], rl[2];
#pragma unroll
    for (int i = 0; i < 2; i++) {
        int c = t + i * 256, r = c >> 2, q = c & 3;
        size_t off = (size_t)(m0 + r) * 128 + q * 8;
        rh[i] = *(const uint4*)(phi + off);
        rl[i] = *(const uint4*)(plo + off);
    }

    float acc[2][4][4];
#pragma unroll
    for (int a = 0; a < 2; a++)
#pragma unroll
        for (int b = 0; b < 4; b++)
#pragma unroll
            for (int q = 0; q < 4; q++) acc[a][b][q] = 0.f;

    int a_row0 = wm + (lane & 15);
    int a_coff = (lane >> 4) * 8;
    int b_kr = (lane & 7) + ((lane >> 3) & 1) * 8;
    int b_nc = wn + (lane >> 4) * 8;

    for (int kc = 0; kc < 4; kc++) {
        uint16_t* buf = sA + (kc & 1) * GA_BUF;
#pragma unroll
        for (int i = 0; i < 2; i++) {
            int c = t + i * 256, r = c >> 2, q = c & 3;
            *(uint4*)(buf + r * GA_STRIDE + q * 8) = rh[i];
            *(uint4*)(buf + GA_PLANE + r * GA_STRIDE + q * 8) = rl[i];
        }
        __syncthreads();

        if (kc < 3) {
#pragma unroll
            for (int i = 0; i < 2; i++) {
                int c = t + i * 256, r = c >> 2, q = c & 3;
                size_t off = (size_t)(m0 + r) * 128 + (kc + 1) * 32 + q * 8;
                rh[i] = *(const uint4*)(phi + off);
                rl[i] = *(const uint4*)(plo + off);
            }
        }

#pragma unroll
        for (int ks = 0; ks < 2; ks++) {
            uint32_t ah[2][4], al[2][4];
#pragma unroll
            for (int mi = 0; mi < 2; mi++) {
                uint32_t ad = smem_u32(buf + (a_row0 + mi * 16) * GA_STRIDE + ks * 16 + a_coff);
                asm volatile("ldmatrix.sync.aligned.m8n8.x4.shared.b16 {%0,%1,%2,%3}, [%4];"
                             : "=r"(ah[mi][0]), "=r"(ah[mi][1]), "=r"(ah[mi][2]), "=r"(ah[mi][3])
                             : "r"(ad));
                uint32_t ad2 = smem_u32(buf + GA_PLANE + (a_row0 + mi * 16) * GA_STRIDE + ks * 16 + a_coff);
                asm volatile("ldmatrix.sync.aligned.m8n8.x4.shared.b16 {%0,%1,%2,%3}, [%4];"
                             : "=r"(al[mi][0]), "=r"(al[mi][1]), "=r"(al[mi][2]), "=r"(al[mi][3])
                             : "r"(ad2));
            }
            uint32_t bh[4][2], bl[4][2];
#pragma unroll
            for (int nt = 0; nt < 2; nt++) {
                int krow = kc * 0 + ks * 16 + b_kr;   // within-chunk k row
                uint32_t ad = smem_u32(sW + (kc * 32 + krow) * GW_STRIDE + b_nc + nt * 16);
                asm volatile("ldmatrix.sync.aligned.m8n8.x4.trans.shared.b16 {%0,%1,%2,%3}, [%4];"
                             : "=r"(bh[nt * 2][0]), "=r"(bh[nt * 2][1]),
                               "=r"(bh[nt * 2 + 1][0]), "=r"(bh[nt * 2 + 1][1])
                             : "r"(ad));
                uint32_t ad2 = smem_u32(sW + 128 * GW_STRIDE + (kc * 32 + krow) * GW_STRIDE + b_nc + nt * 16);
                asm volatile("ldmatrix.sync.aligned.m8n8.x4.trans.shared.b16 {%0,%1,%2,%3}, [%4];"
                             : "=r"(bl[nt * 2][0]), "=r"(bl[nt * 2][1]),
                               "=r"(bl[nt * 2 + 1][0]), "=r"(bl[nt * 2 + 1][1])
                             : "r"(ad2));
            }
#pragma unroll
            for (int mi = 0; mi < 2; mi++)
#pragma unroll
                for (int nj = 0; nj < 4; nj++) {
                    asm volatile(
                        "mma.sync.aligned.m16n8k16.row.col.f32.bf16.bf16.f32 "
                        "{%0,%1,%2,%3}, {%4,%5,%6,%7}, {%8,%9}, {%0,%1,%2,%3};"
                        : "+f"(acc[mi][nj][0]), "+f"(acc[mi][nj][1]),
                          "+f"(acc[mi][nj][2]), "+f"(acc[mi][nj][3])
                        : "r"(ah[mi][0]), "r"(ah[mi][1]), "r"(ah[mi][2]), "r"(ah[mi][3]),
                          "r"(bh[nj][0]), "r"(bh[nj][1]));
                    asm volatile(
                        "mma.sync.aligned.m16n8k16.row.col.f32.bf16.bf16.f32 "
                        "{%0,%1,%2,%3}, {%4,%5,%6,%7}, {%8,%9}, {%0,%1,%2,%3};"
                        : "+f"(acc[mi][nj][0]), "+f"(acc[mi][nj][1]),
                          "+f"(acc[mi][nj][2]), "+f"(acc[mi][nj][3])
                        : "r"(al[mi][0]), "r"(al[mi][1]), "r"(al[mi][2]), "r"(al[mi][3]),
                          "r"(bh[nj][0]), "r"(bh[nj][1]));
                    asm volatile(
                        "mma.sync.aligned.m16n8k16.row.col.f32.bf16.bf16.f32 "
                        "{%0,%1,%2,%3}, {%4,%5,%6,%7}, {%8,%9}, {%0,%1,%2,%3};"
                        : "+f"(acc[mi][nj][0]), "+f"(acc[mi][nj][1]),
                          "+f"(acc[mi][nj][2]), "+f"(acc[mi][nj][3])
                        : "r"(ah[mi][0]), "r"(ah[mi][1]), "r"(ah[mi][2]), "r"(ah[mi][3]),
                          "r"(bl[nj][0]), "r"(bl[nj][1]));
                }
        }
        __syncthreads();
    }

    // epilogue
#pragma unroll
    for (int mi = 0; mi < 2; mi++) {
        int row = m0 + wm + mi * 16 + (lane >> 2);
#pragma unroll
        for (int nj = 0; nj < 4; nj++) {
            int col = cb + wn + nj * 8 + (lane & 3) * 2;
            *(float2*)(C + (size_t)row * 128 + col) = make_float2(acc[mi][nj][0], acc[mi][nj][1]);
            *(float2*)(C + (size_t)(row + 8) * 128 + col) = make_float2(acc[mi][nj][2], acc[mi][nj][3]);
        }
    }
}

// ---------------- aggregate: warp-per-node, 32-col quarter blocks, 2 CTA/SM ----------------
// out[n,c] = relu(bias + dn^2*xw[n,c] + dn * sum_s dis[s]*xw[s,c]); optional bf16 planes
#define AGG_SMEM ((512 * 34 + 512) * 4)
template <bool PLANES>
__global__ void __launch_bounds__(512, 2)
k_agg(const float* __restrict__ bias, float* __restrict__ out) {
    extern __shared__ float sma[];
    float* sX = sma;             // [512][34]
    float* sD = sma + 512 * 34;  // [512]

    int g = blockIdx.y;
    int c0 = blockIdx.x * 32;
    int t = threadIdx.x, w = t >> 5, l = t & 31;
    int nb = g * N_PG;

    for (int row = w; row < N_PG; row += 16)
        sX[row * 34 + l] = g_xw[(size_t)(nb + row) * 128 + c0 + l];
    sD[t] = g_dis[nb + t];
    __syncthreads();

    float bv = bias[c0 + l];
    for (int n = w; n < N_PG; n += 16) {
        float dn = sD[n];
        float acc = dn * dn * sX[n * 34 + l];
        int base = g_off[nb + n];
        int d = g_deg[nb + n];
        int sj = (d > 0) ? g_csr[base] : 0;
        for (int j = 0; j < d; j++) {
            int snx = (j + 1 < d) ? g_csr[base + j + 1] : 0;
            acc += dn * sD[sj] * sX[sj * 34 + l];
            sj = snx;
        }
        float v = fmaxf(acc + bv, 0.f);
        out[(size_t)(nb + n) * 384 + c0 + l] = v;
        if (PLANES) {
            __nv_bfloat16 hi = __float2bfloat16_rn(v);
            g_ahi[(size_t)(nb + n) * 128 + c0 + l] = hi;
            g_alo[(size_t)(nb + n) * 128 + c0 + l] =
                __float2bfloat16_rn(v - __bfloat162float(hi));
        }
    }
}

// ---------------- fused score GEMV + score aggregate + top-k + gated readout ----------------
__global__ void k_spool(const float* __restrict__ Wsc, const float* __restrict__ bs) {
    __shared__ float ws[384];
    __shared__ float spre[N_PG];
    __shared__ float dss[N_PG];
    __shared__ float scr[N_PG];
    __shared__ unsigned long long key[N_PG];
    __shared__ int sel[K_SEL];
    __shared__ float gate[K_SEL];

    int g = blockIdx.x, t = threadIdx.x;    // 512 threads
    int nb = g * N_PG;
    if (t < 384) ws[t] = Wsc[t];
    dss[t] = g_dis[nb + t];
    __syncthreads();

    int w = t >> 5, lane = t & 31;
    for (int i = 0; i < 32; i++) {
        int n = i * 16 + w;
        const float* h = g_h + (size_t)(nb + n) * 384;
        float acc = 0.f;
#pragma unroll
        for (int c = lane * 4; c < 384; c += 128) {
            float4 hv = *(const float4*)(h + c);
            float4 wv = *(const float4*)(ws + c);
            acc += hv.x * wv.x + hv.y * wv.y + hv.z * wv.z + hv.w * wv.w;
        }
#pragma unroll
        for (int o = 16; o; o >>= 1) acc += __shfl_xor_sync(0xffffffffu, acc, o);
        if (lane == 0) spre[n] = acc;
    }
    __syncthreads();

    float dn = dss[t];
    float sc = dn * dn * spre[t];
    int base = g_off[nb + t], d = g_deg[nb + t];
    for (int j = 0; j < d; j++) {
        int s = g_csr[base + j];
        sc += dn * dss[s] * spre[s];
    }
    sc += bs[0];
    scr[t] = sc;

    unsigned u = __float_as_uint(sc);
    u = (u & 0x80000000u) ? ~u : (u ^ 0x80000000u);
    u = ~u;                                  // descending order
    key[t] = ((unsigned long long)u << 32) | (unsigned)t;
    __syncthreads();

    for (int k = 2; k <= N_PG; k <<= 1) {
        for (int j = k >> 1; j > 0; j >>= 1) {
            int ixj = t ^ j;
            if (ixj > t) {
                unsigned long long a = key[t], b = key[ixj];
                bool up = ((t & k) == 0);
                if ((a > b) == up) { key[t] = b; key[ixj] = a; }
            }
            __syncthreads();
        }
    }

    if (t < K_SEL) {
        int idx = (int)(key[t] & 0xffffffffu);
        sel[t] = idx;
        gate[t] = tanhf(scr[idx]);
    }
    __syncthreads();

    if (t < 384) {
        float vmax = __int_as_float(0xff800000);
        float vsum = 0.f;
        const float* hb = g_h + (size_t)nb * 384;
        for (int i = 0; i < K_SEL; i++) {
            float v = hb[(size_t)sel[i] * 384 + t] * gate[i];
            vmax = fmaxf(vmax, v);
            vsum += v;
        }
        g_read[g * 768 + t] = vmax;
        g_read[g * 768 + 384 + t] = vsum * (1.0f / K_SEL);
    }
}

// ---------------- small SGEMM (MLP head): C = A(MxK)*B(KxN), bias+relu ----------------
__global__ void k_sgemm_br(const float* __restrict__ A, int lda,
                           const float* __restrict__ B, int ldb,
                           const float* __restrict__ bias,
                           float* __restrict__ C, int ldc, int Kdim) {
    __shared__ float As[16][68];
    __shared__ float Bs[16][68];
    int tid = threadIdx.x;
    int tx = tid & 15, ty = tid >> 4;
    int arow = tid >> 2, acol = (tid & 3) * 4;
    int brow = tid >> 4, bcol = (tid & 15) * 4;
    int row0 = blockIdx.y * 64, col0 = blockIdx.x * 64;
    const float* Aptr = A + (size_t)(row0 + arow) * lda + acol;
    const float* Bptr = B + (size_t)brow * ldb + col0 + bcol;
    float acc[4][4];
#pragma unroll
    for (int i = 0; i < 4; i++)
#pragma unroll
        for (int j = 0; j < 4; j++) acc[i][j] = 0.f;
    for (int k0 = 0; k0 < Kdim; k0 += 16) {
        float4 a = *(const float4*)(Aptr + k0);
        float4 b = *(const float4*)(Bptr + (size_t)k0 * ldb);
        As[acol + 0][arow] = a.x; As[acol + 1][arow] = a.y;
        As[acol + 2][arow] = a.z; As[acol + 3][arow] = a.w;
        *(float4*)&Bs[brow][bcol] = b;
        __syncthreads();
#pragma unroll
        for (int k = 0; k < 16; k++) {
            float ar[4], br[4];
            *(float4*)ar = *(const float4*)&As[k][ty * 4];
            *(float4*)br = *(const float4*)&Bs[k][tx * 4];
#pragma unroll
            for (int i = 0; i < 4; i++)
#pragma unroll
                for (int j = 0; j < 4; j++) acc[i][j] += ar[i] * br[j];
        }
        __syncthreads();
    }
#pragma unroll
    for (int i = 0; i < 4; i++)
#pragma unroll
        for (int j = 0; j < 4; j++) {
            int col = col0 + tx * 4 + j;
            C[(size_t)(row0 + ty * 4 + i) * ldc + col] =
                fmaxf(acc[i][j] + bias[col], 0.f);
        }
}

// ---------------- final layer + log_softmax ----------------
__global__ void k_final(const float* __restrict__ Wl3, const float* __restrict__ bl3,
                        float* __restrict__ out) {
    int r = blockIdx.x;
    int lane = threadIdx.x;
    float4 zv = *(const float4*)(g_z2 + r * 128 + lane * 4);
    float logits[10];
#pragma unroll
    for (int o = 0; o < 10; o++) {
        int k = lane * 4;
        float p = zv.x * Wl3[(k + 0) * 10 + o] + zv.y * Wl3[(k + 1) * 10 + o] +
                  zv.z * Wl3[(k + 2) * 10 + o] + zv.w * Wl3[(k + 3) * 10 + o];
#pragma unroll
        for (int s = 16; s; s >>= 1) p += __shfl_xor_sync(0xffffffffu, p, s);
        logits[o] = p + bl3[o];
    }
    if (lane == 0) {
        float m = logits[0];
#pragma unroll
        for (int o = 1; o < 10; o++) m = fmaxf(m, logits[o]);
        float se = 0.f;
#pragma unroll
        for (int o = 0; o < 10; o++) se += expf(logits[o] - m);
        float lse = m + logf(se);
#pragma unroll
        for (int o = 0; o < 10; o++) out[r * 10 + o] = logits[o] - lse;
    }
}

// ---------------- launcher ----------------
extern "C" void kernel_launch(void* const* d_in, const int* in_sizes, int n_in,
                              void* d_out, int out_size) {
    const float* x   = (const float*)d_in[0];
    const int*   ei  = (const int*)d_in[1];
    const float* W1  = (const float*)d_in[2];
    const float* b1  = (const float*)d_in[3];
    const float* W2  = (const float*)d_in[4];
    const float* b2  = (const float*)d_in[5];
    const float* W3  = (const float*)d_in[6];
    const float* b3  = (const float*)d_in[7];
    const float* Ws  = (const float*)d_in[8];
    const float* bs  = (const float*)d_in[9];
    const float* Wl1 = (const float*)d_in[10];
    const float* bl1 = (const float*)d_in[11];
    const float* Wl2 = (const float*)d_in[12];
    const float* bl2 = (const float*)d_in[13];
    const float* Wl3 = (const float*)d_in[14];
    const float* bl3 = (const float*)d_in[15];

    const int* src = ei;
    const int* dst = ei + N_E;

    static int attr_done = 0;
    if (!attr_done) {
        cudaFuncSetAttribute(k_gemm_tc, cudaFuncAttributeMaxDynamicSharedMemorySize, GEMM_SMEM);
        cudaFuncSetAttribute(k_agg<true>, cudaFuncAttributeMaxDynamicSharedMemorySize, AGG_SMEM);
        cudaFuncSetAttribute(k_agg<false>, cudaFuncAttributeMaxDynamicSharedMemorySize, AGG_SMEM);
        attr_done = 1;
    }

    void* p;
    cudaGetSymbolAddress(&p, g_xw);   float* xw = (float*)p;
    cudaGetSymbolAddress(&p, g_h);    float* h  = (float*)p;
    cudaGetSymbolAddress(&p, g_read); float* rd = (float*)p;
    cudaGetSymbolAddress(&p, g_z1);   float* z1 = (float*)p;
    cudaGetSymbolAddress(&p, g_z2);   float* z2 = (float*)p;

    k_prep<<<B_G, N_PG>>>(src, dst);
    k_xconv<<<(N_NODES * 128 / 4) / 256, 256>>>(x);

    dim3 gg(2, N_NODES / 128);
    dim3 ga(4, B_G);
    k_gemm_tc<<<gg, 256, GEMM_SMEM>>>(W1, xw);
    k_agg<true><<<ga, 512, AGG_SMEM>>>(b1, h + 0);
    k_gemm_tc<<<gg, 256, GEMM_SMEM>>>(W2, xw);
    k_agg<true><<<ga, 512, AGG_SMEM>>>(b2, h + 128);
    k_gemm_tc<<<gg, 256, GEMM_SMEM>>>(W3, xw);
    k_agg<false><<<ga, 512, AGG_SMEM>>>(b3, h + 256);

    k_spool<<<B_G, N_PG>>>(Ws, bs);

    k_sgemm_br<<<dim3(4, 2), 256>>>(rd, 768, Wl1, 256, bl1, z1, 256, 768);
    k_sgemm_br<<<dim3(2, 2), 256>>>(z1, 256, Wl2, 128, bl2, z2, 128, 256);
    k_final<<<B_G, 32>>>(Wl3, bl3, (float*)d_out);
}

// round 5
// speedup vs baseline: 1.2523x; 1.2523x over previous
#include <cuda_runtime.h>
#include <cuda_bf16.h>
#include <math.h>
#include <stdint.h>

#define N_NODES 65536
#define B_G     128
#define N_PG    512
#define N_E     1048576
#define K_SEL   256
#define EPG     8192

// ---------------- scratch ----------------
__device__ int   g_deg[N_NODES];
__device__ int   g_off[N_NODES];
__device__ float g_dis[N_NODES];
__device__ int   g_csr[N_E];            // graph-LOCAL source indices
__device__ float g_xw[(size_t)N_NODES * 128];
__device__ float g_h[(size_t)N_NODES * 384];
__device__ __nv_bfloat16 g_ahi[(size_t)N_NODES * 128];   // GEMM A input, hi plane
__device__ __nv_bfloat16 g_alo[(size_t)N_NODES * 128];   // GEMM A input, lo plane
__device__ float g_read[B_G * 768];
__device__ float g_z1[B_G * 256];
__device__ float g_z2[B_G * 128];

// ---------------- fused preprocessing: one block per graph ----------------
__global__ void k_prep(const int* __restrict__ src, const int* __restrict__ dst) {
    __shared__ int degs[N_PG];
    __shared__ int curs[N_PG];
    __shared__ int csr[EPG];
    int g = blockIdx.x, t = threadIdx.x;     // 512 threads
    int nb = g * N_PG, eb = g * EPG;

    degs[t] = 0;
    __syncthreads();
    for (int e = t; e < EPG; e += N_PG) atomicAdd(&degs[dst[eb + e] - nb], 1);
    __syncthreads();

    int d = degs[t];
    curs[t] = d;
    __syncthreads();
    for (int off = 1; off < N_PG; off <<= 1) {
        int v = (t >= off) ? curs[t - off] : 0;
        __syncthreads();
        curs[t] += v;
        __syncthreads();
    }
    int excl = curs[t] - d;
    g_off[nb + t] = eb + excl;
    g_deg[nb + t] = d;
    g_dis[nb + t] = rsqrtf((float)(d + 1));
    curs[t] = excl;
    __syncthreads();

    for (int e = t; e < EPG; e += N_PG) {
        int dl = dst[eb + e] - nb;
        int p = atomicAdd(&curs[dl], 1);
        csr[p] = src[eb + e] - nb;           // local src
    }
    __syncthreads();
    for (int e = t; e < EPG; e += N_PG) g_csr[eb + e] = csr[e];
}

// ---------------- split helpers ----------------
__device__ __forceinline__ void split_pack(float x, float y, uint32_t& hi, uint32_t& lo) {
    __nv_bfloat16 hx = __float2bfloat16_rn(x);
    __nv_bfloat16 hy = __float2bfloat16_rn(y);
    __nv_bfloat16 lx = __float2bfloat16_rn(x - __bfloat162float(hx));
    __nv_bfloat16 ly = __float2bfloat16_rn(y - __bfloat162float(hy));
    hi = ((uint32_t)*(uint16_t*)&hy << 16) | *(uint16_t*)&hx;
    lo = ((uint32_t)*(uint16_t*)&ly << 16) | *(uint16_t*)&lx;
}
__device__ __forceinline__ uint32_t smem_u32(const void* p) {
    return (uint32_t)__cvta_generic_to_shared(p);
}

// ---------------- x -> bf16 hi/lo planes ----------------
__global__ void k_xconv(const float* __restrict__ x) {
    size_t i = (size_t)blockIdx.x * 256 + threadIdx.x;   // float4 index
    float4 v = ((const float4*)x)[i];
    uint32_t h0, l0, h1, l1;
    split_pack(v.x, v.y, h0, l0);
    split_pack(v.z, v.w, h1, l1);
    *(uint2*)((uint16_t*)g_ahi + i * 4) = make_uint2(h0, h1);
    *(uint2*)((uint16_t*)g_alo + i * 4) = make_uint2(l0, l1);
}

// ---------------- tensor-core GEMM (bf16x3): xw[M,128] = planes(A)[M,128] @ W[128,128] ----------------
#define GW_STRIDE 72
#define GA_STRIDE 56
#define GA_PLANE  (128 * GA_STRIDE)
#define GA_BUF    (2 * GA_PLANE)
#define GEMM_SMEM ((2 * 128 * GW_STRIDE + 2 * GA_BUF) * 2)

__global__ void __launch_bounds__(256, 2)
k_gemm_tc(const float* __restrict__ W, float* __restrict__ C) {
    extern __shared__ uint16_t smg[];
    uint16_t* sW = smg;                        // 2 planes x 128 x 72
    uint16_t* sA = smg + 2 * 128 * GW_STRIDE;  // 2 bufs x 2 planes x 128 x 56

    int t = threadIdx.x;
    int cb = blockIdx.x * 64;
    int m0 = blockIdx.y * 128;
    int wid = t >> 5, lane = t & 31;
    int wm = (wid & 3) * 32, wn = (wid >> 2) * 32;

    for (int idx = t; idx < 128 * 16; idx += 256) {
        int k = idx >> 4, cq = (idx & 15) * 4;
        float4 v = *(const float4*)(W + k * 128 + cb + cq);
        uint32_t h0, l0, h1, l1;
        split_pack(v.x, v.y, h0, l0);
        split_pack(v.z, v.w, h1, l1);
        *(uint2*)(sW + k * GW_STRIDE + cq) = make_uint2(h0, h1);
        *(uint2*)(sW + 128 * GW_STRIDE + k * GW_STRIDE + cq) = make_uint2(l0, l1);
    }

    const uint16_t* phi = (const uint16_t*)g_ahi;
    const uint16_t* plo = (const uint16_t*)g_alo;
    uint4 rh[2], rl[2];
#pragma unroll
    for (int i = 0; i < 2; i++) {
        int c = t + i * 256, r = c >> 2, q = c & 3;
        size_t off = (size_t)(m0 + r) * 128 + q * 8;
        rh[i] = *(const uint4*)(phi + off);
        rl[i] = *(const uint4*)(plo + off);
    }

    float acc[2][4][4];
#pragma unroll
    for (int a = 0; a < 2; a++)
#pragma unroll
        for (int b = 0; b < 4; b++)
#pragma unroll
            for (int q = 0; q < 4; q++) acc[a][b][q] = 0.f;

    int a_row0 = wm + (lane & 15);
    int a_coff = (lane >> 4) * 8;
    int b_kr = (lane & 7) + ((lane >> 3) & 1) * 8;
    int b_nc = wn + (lane >> 4) * 8;

    for (int kc = 0; kc < 4; kc++) {
        uint16_t* buf = sA + (kc & 1) * GA_BUF;
#pragma unroll
        for (int i = 0; i < 2; i++) {
            int c = t + i * 256, r = c >> 2, q = c & 3;
            *(uint4*)(buf + r * GA_STRIDE + q * 8) = rh[i];
            *(uint4*)(buf + GA_PLANE + r * GA_STRIDE + q * 8) = rl[i];
        }
        __syncthreads();

        if (kc < 3) {
#pragma unroll
            for (int i = 0; i < 2; i++) {
                int c = t + i * 256, r = c >> 2, q = c & 3;
                size_t off = (size_t)(m0 + r) * 128 + (kc + 1) * 32 + q * 8;
                rh[i] = *(const uint4*)(phi + off);
                rl[i] = *(const uint4*)(plo + off);
            }
        }

#pragma unroll
        for (int ks = 0; ks < 2; ks++) {
            uint32_t ah[2][4], al[2][4];
#pragma unroll
            for (int mi = 0; mi < 2; mi++) {
                uint32_t ad = smem_u32(buf + (a_row0 + mi * 16) * GA_STRIDE + ks * 16 + a_coff);
                asm volatile("ldmatrix.sync.aligned.m8n8.x4.shared.b16 {%0,%1,%2,%3}, [%4];"
                             : "=r"(ah[mi][0]), "=r"(ah[mi][1]), "=r"(ah[mi][2]), "=r"(ah[mi][3])
                             : "r"(ad));
                uint32_t ad2 = smem_u32(buf + GA_PLANE + (a_row0 + mi * 16) * GA_STRIDE + ks * 16 + a_coff);
                asm volatile("ldmatrix.sync.aligned.m8n8.x4.shared.b16 {%0,%1,%2,%3}, [%4];"
                             : "=r"(al[mi][0]), "=r"(al[mi][1]), "=r"(al[mi][2]), "=r"(al[mi][3])
                             : "r"(ad2));
            }
            uint32_t bh[4][2], bl[4][2];
#pragma unroll
            for (int nt = 0; nt < 2; nt++) {
                int krow = ks * 16 + b_kr;
                uint32_t ad = smem_u32(sW + (kc * 32 + krow) * GW_STRIDE + b_nc + nt * 16);
                asm volatile("ldmatrix.sync.aligned.m8n8.x4.trans.shared.b16 {%0,%1,%2,%3}, [%4];"
                             : "=r"(bh[nt * 2][0]), "=r"(bh[nt * 2][1]),
                               "=r"(bh[nt * 2 + 1][0]), "=r"(bh[nt * 2 + 1][1])
                             : "r"(ad));
                uint32_t ad2 = smem_u32(sW + 128 * GW_STRIDE + (kc * 32 + krow) * GW_STRIDE + b_nc + nt * 16);
                asm volatile("ldmatrix.sync.aligned.m8n8.x4.trans.shared.b16 {%0,%1,%2,%3}, [%4];"
                             : "=r"(bl[nt * 2][0]), "=r"(bl[nt * 2][1]),
                               "=r"(bl[nt * 2 + 1][0]), "=r"(bl[nt * 2 + 1][1])
                             : "r"(ad2));
            }
#pragma unroll
            for (int mi = 0; mi < 2; mi++)
#pragma unroll
                for (int nj = 0; nj < 4; nj++) {
                    asm volatile(
                        "mma.sync.aligned.m16n8k16.row.col.f32.bf16.bf16.f32 "
                        "{%0,%1,%2,%3}, {%4,%5,%6,%7}, {%8,%9}, {%0,%1,%2,%3};"
                        : "+f"(acc[mi][nj][0]), "+f"(acc[mi][nj][1]),
                          "+f"(acc[mi][nj][2]), "+f"(acc[mi][nj][3])
                        : "r"(ah[mi][0]), "r"(ah[mi][1]), "r"(ah[mi][2]), "r"(ah[mi][3]),
                          "r"(bh[nj][0]), "r"(bh[nj][1]));
                    asm volatile(
                        "mma.sync.aligned.m16n8k16.row.col.f32.bf16.bf16.f32 "
                        "{%0,%1,%2,%3}, {%4,%5,%6,%7}, {%8,%9}, {%0,%1,%2,%3};"
                        : "+f"(acc[mi][nj][0]), "+f"(acc[mi][nj][1]),
                          "+f"(acc[mi][nj][2]), "+f"(acc[mi][nj][3])
                        : "r"(al[mi][0]), "r"(al[mi][1]), "r"(al[mi][2]), "r"(al[mi][3]),
                          "r"(bh[nj][0]), "r"(bh[nj][1]));
                    asm volatile(
                        "mma.sync.aligned.m16n8k16.row.col.f32.bf16.bf16.f32 "
                        "{%0,%1,%2,%3}, {%4,%5,%6,%7}, {%8,%9}, {%0,%1,%2,%3};"
                        : "+f"(acc[mi][nj][0]), "+f"(acc[mi][nj][1]),
                          "+f"(acc[mi][nj][2]), "+f"(acc[mi][nj][3])
                        : "r"(ah[mi][0]), "r"(ah[mi][1]), "r"(ah[mi][2]), "r"(ah[mi][3]),
                          "r"(bl[nj][0]), "r"(bl[nj][1]));
                }
        }
        __syncthreads();
    }

#pragma unroll
    for (int mi = 0; mi < 2; mi++) {
        int row = m0 + wm + mi * 16 + (lane >> 2);
#pragma unroll
        for (int nj = 0; nj < 4; nj++) {
            int col = cb + wn + nj * 8 + (lane & 3) * 2;
            *(float2*)(C + (size_t)row * 128 + col) = make_float2(acc[mi][nj][0], acc[mi][nj][1]);
            *(float2*)(C + (size_t)(row + 8) * 128 + col) = make_float2(acc[mi][nj][2], acc[mi][nj][3]);
        }
    }
}

// ---------------- aggregate v2: warp-per-node over 64-col half tile, all-SMEM gather ----------------
// sX 512x64 fp32 (128KB) + csr (32KB) + dis/off/deg (6KB) = 166KB, 1 CTA/SM, grid (2, 128)
#define AGG_SMEM (512 * 64 * 4 + EPG * 4 + 512 * 4 * 3)
template <bool PLANES>
__global__ void __launch_bounds__(512, 1)
k_agg(const float* __restrict__ bias, float* __restrict__ out) {
    extern __shared__ float sma[];
    float* sX   = sma;                    // [512][64]
    float* sD   = sma + 512 * 64;         // [512]
    int*   sOff = (int*)(sD + 512);       // [512] local
    int*   sDeg = sOff + 512;             // [512]
    int*   sCsr = sDeg + 512;             // [8192]

    int g = blockIdx.y, c0 = blockIdx.x * 64, t = threadIdx.x;
    int nb = g * N_PG, eb = g * EPG;

    for (int i = t; i < 512 * 16; i += 512) {
        int row = i >> 4, cq = (i & 15) * 4;
        *(float4*)&sX[row * 64 + cq] =
            *(const float4*)(g_xw + (size_t)(nb + row) * 128 + c0 + cq);
    }
    sD[t]   = g_dis[nb + t];
    sOff[t] = g_off[nb + t] - eb;
    sDeg[t] = g_deg[nb + t];
    for (int e = t * 4; e < EPG; e += 512 * 4)
        *(int4*)&sCsr[e] = *(const int4*)(g_csr + eb + e);
    __syncthreads();

    int w = t >> 5, lane = t & 31;
    const float2* sX2 = (const float2*)sX;
    float2 bb = *(const float2*)(bias + c0 + lane * 2);

    for (int n = w; n < N_PG; n += 16) {
        float dn = sD[n];
        float2 v = sX2[n * 32 + lane];
        float s2 = dn * dn;
        float ax = s2 * v.x, ay = s2 * v.y;
        int base = sOff[n], d = sDeg[n];
        if (d > 0) {
            int sj = sCsr[base];
            float2 u = sX2[sj * 32 + lane];
            float wg = dn * sD[sj];
            for (int j = 0; j < d; j++) {
                int nx = (j + 1 < d) ? sCsr[base + j + 1] : 0;
                float2 un = sX2[nx * 32 + lane];
                float wn = dn * sD[nx];
                ax += wg * u.x;
                ay += wg * u.y;
                u = un; wg = wn;
            }
        }
        float ox = fmaxf(ax + bb.x, 0.f);
        float oy = fmaxf(ay + bb.y, 0.f);
        *(float2*)(out + (size_t)(nb + n) * 384 + c0 + lane * 2) = make_float2(ox, oy);
        if (PLANES) {
            size_t po = (size_t)(nb + n) * 128 + c0 + lane * 2;
            __nv_bfloat16 hx = __float2bfloat16_rn(ox);
            __nv_bfloat16 hy = __float2bfloat16_rn(oy);
            uint32_t hp = ((uint32_t)*(uint16_t*)&hy << 16) | *(uint16_t*)&hx;
            __nv_bfloat16 lx = __float2bfloat16_rn(ox - __bfloat162float(hx));
            __nv_bfloat16 ly = __float2bfloat16_rn(oy - __bfloat162float(hy));
            uint32_t lp = ((uint32_t)*(uint16_t*)&ly << 16) | *(uint16_t*)&lx;
            *(uint32_t*)((uint16_t*)g_ahi + po) = hp;
            *(uint32_t*)((uint16_t*)g_alo + po) = lp;
        }
    }
}

// ---------------- fused score GEMV + score aggregate + top-k + gated readout ----------------
__global__ void k_spool(const float* __restrict__ Wsc, const float* __restrict__ bs) {
    __shared__ float ws[384];
    __shared__ float spre[N_PG];
    __shared__ float dss[N_PG];
    __shared__ float scr[N_PG];
    __shared__ unsigned long long key[N_PG];
    __shared__ int sel[K_SEL];
    __shared__ float gate[K_SEL];

    int g = blockIdx.x, t = threadIdx.x;    // 512 threads
    int nb = g * N_PG;
    if (t < 384) ws[t] = Wsc[t];
    dss[t] = g_dis[nb + t];
    __syncthreads();

    int w = t >> 5, lane = t & 31;
    for (int i = 0; i < 32; i++) {
        int n = i * 16 + w;
        const float* h = g_h + (size_t)(nb + n) * 384;
        float acc = 0.f;
#pragma unroll
        for (int c = lane * 4; c < 384; c += 128) {
            float4 hv = *(const float4*)(h + c);
            float4 wv = *(const float4*)(ws + c);
            acc += hv.x * wv.x + hv.y * wv.y + hv.z * wv.z + hv.w * wv.w;
        }
#pragma unroll
        for (int o = 16; o; o >>= 1) acc += __shfl_xor_sync(0xffffffffu, acc, o);
        if (lane == 0) spre[n] = acc;
    }
    __syncthreads();

    float dn = dss[t];
    float sc = dn * dn * spre[t];
    int base = g_off[nb + t], d = g_deg[nb + t];
    for (int j = 0; j < d; j++) {
        int s = g_csr[base + j];
        sc += dn * dss[s] * spre[s];
    }
    sc += bs[0];
    scr[t] = sc;

    unsigned u = __float_as_uint(sc);
    u = (u & 0x80000000u) ? ~u : (u ^ 0x80000000u);
    u = ~u;                                  // descending order
    key[t] = ((unsigned long long)u << 32) | (unsigned)t;
    __syncthreads();

    for (int k = 2; k <= N_PG; k <<= 1) {
        for (int j = k >> 1; j > 0; j >>= 1) {
            int ixj = t ^ j;
            if (ixj > t) {
                unsigned long long a = key[t], b = key[ixj];
                bool up = ((t & k) == 0);
                if ((a > b) == up) { key[t] = b; key[ixj] = a; }
            }
            __syncthreads();
        }
    }

    if (t < K_SEL) {
        int idx = (int)(key[t] & 0xffffffffu);
        sel[t] = idx;
        gate[t] = tanhf(scr[idx]);
    }
    __syncthreads();

    if (t < 384) {
        float vmax = __int_as_float(0xff800000);
        float vsum = 0.f;
        const float* hb = g_h + (size_t)nb * 384;
        for (int i = 0; i < K_SEL; i++) {
            float v = hb[(size_t)sel[i] * 384 + t] * gate[i];
            vmax = fmaxf(vmax, v);
            vsum += v;
        }
        g_read[g * 768 + t] = vmax;
        g_read[g * 768 + 384 + t] = vsum * (1.0f / K_SEL);
    }
}

// ---------------- small SGEMM (MLP head): C = A(MxK)*B(KxN), bias+relu ----------------
__global__ void k_sgemm_br(const float* __restrict__ A, int lda,
                           const float* __restrict__ B, int ldb,
                           const float* __restrict__ bias,
                           float* __restrict__ C, int ldc, int Kdim) {
    __shared__ float As[16][68];
    __shared__ float Bs[16][68];
    int tid = threadIdx.x;
    int tx = tid & 15, ty = tid >> 4;
    int arow = tid >> 2, acol = (tid & 3) * 4;
    int brow = tid >> 4, bcol = (tid & 15) * 4;
    int row0 = blockIdx.y * 64, col0 = blockIdx.x * 64;
    const float* Aptr = A + (size_t)(row0 + arow) * lda + acol;
    const float* Bptr = B + (size_t)brow * ldb + col0 + bcol;
    float acc[4][4];
#pragma unroll
    for (int i = 0; i < 4; i++)
#pragma unroll
        for (int j = 0; j < 4; j++) acc[i][j] = 0.f;
    for (int k0 = 0; k0 < Kdim; k0 += 16) {
        float4 a = *(const float4*)(Aptr + k0);
        float4 b = *(const float4*)(Bptr + (size_t)k0 * ldb);
        As[acol + 0][arow] = a.x; As[acol + 1][arow] = a.y;
        As[acol + 2][arow] = a.z; As[acol + 3][arow] = a.w;
        *(float4*)&Bs[brow][bcol] = b;
        __syncthreads();
#pragma unroll
        for (int k = 0; k < 16; k++) {
            float ar[4], br[4];
            *(float4*)ar = *(const float4*)&As[k][ty * 4];
            *(float4*)br = *(const float4*)&Bs[k][tx * 4];
#pragma unroll
            for (int i = 0; i < 4; i++)
#pragma unroll
                for (int j = 0; j < 4; j++) acc[i][j] += ar[i] * br[j];
        }
        __syncthreads();
    }
#pragma unroll
    for (int i = 0; i < 4; i++)
#pragma unroll
        for (int j = 0; j < 4; j++) {
            int col = col0 + tx * 4 + j;
            C[(size_t)(row0 + ty * 4 + i) * ldc + col] =
                fmaxf(acc[i][j] + bias[col], 0.f);
        }
}

// ---------------- final layer + log_softmax ----------------
__global__ void k_final(const float* __restrict__ Wl3, const float* __restrict__ bl3,
                        float* __restrict__ out) {
    int r = blockIdx.x;
    int lane = threadIdx.x;
    float4 zv = *(const float4*)(g_z2 + r * 128 + lane * 4);
    float logits[10];
#pragma unroll
    for (int o = 0; o < 10; o++) {
        int k = lane * 4;
        float p = zv.x * Wl3[(k + 0) * 10 + o] + zv.y * Wl3[(k + 1) * 10 + o] +
                  zv.z * Wl3[(k + 2) * 10 + o] + zv.w * Wl3[(k + 3) * 10 + o];
#pragma unroll
        for (int s = 16; s; s >>= 1) p += __shfl_xor_sync(0xffffffffu, p, s);
        logits[o] = p + bl3[o];
    }
    if (lane == 0) {
        float m = logits[0];
#pragma unroll
        for (int o = 1; o < 10; o++) m = fmaxf(m, logits[o]);
        float se = 0.f;
#pragma unroll
        for (int o = 0; o < 10; o++) se += expf(logits[o] - m);
        float lse = m + logf(se);
#pragma unroll
        for (int o = 0; o < 10; o++) out[r * 10 + o] = logits[o] - lse;
    }
}

// ---------------- launcher ----------------
extern "C" void kernel_launch(void* const* d_in, const int* in_sizes, int n_in,
                              void* d_out, int out_size) {
    const float* x   = (const float*)d_in[0];
    const int*   ei  = (const int*)d_in[1];
    const float* W1  = (const float*)d_in[2];
    const float* b1  = (const float*)d_in[3];
    const float* W2  = (const float*)d_in[4];
    const float* b2  = (const float*)d_in[5];
    const float* W3  = (const float*)d_in[6];
    const float* b3  = (const float*)d_in[7];
    const float* Ws  = (const float*)d_in[8];
    const float* bs  = (const float*)d_in[9];
    const float* Wl1 = (const float*)d_in[10];
    const float* bl1 = (const float*)d_in[11];
    const float* Wl2 = (const float*)d_in[12];
    const float* bl2 = (const float*)d_in[13];
    const float* Wl3 = (const float*)d_in[14];
    const float* bl3 = (const float*)d_in[15];

    const int* src = ei;
    const int* dst = ei + N_E;

    static int attr_done = 0;
    if (!attr_done) {
        cudaFuncSetAttribute(k_gemm_tc, cudaFuncAttributeMaxDynamicSharedMemorySize, GEMM_SMEM);
        cudaFuncSetAttribute(k_agg<true>, cudaFuncAttributeMaxDynamicSharedMemorySize, AGG_SMEM);
        cudaFuncSetAttribute(k_agg<false>, cudaFuncAttributeMaxDynamicSharedMemorySize, AGG_SMEM);
        attr_done = 1;
    }

    void* p;
    cudaGetSymbolAddress(&p, g_xw);   float* xw = (float*)p;
    cudaGetSymbolAddress(&p, g_h);    float* h  = (float*)p;
    cudaGetSymbolAddress(&p, g_read); float* rd = (float*)p;
    cudaGetSymbolAddress(&p, g_z1);   float* z1 = (float*)p;
    cudaGetSymbolAddress(&p, g_z2);   float* z2 = (float*)p;

    k_prep<<<B_G, N_PG>>>(src, dst);
    k_xconv<<<(N_NODES * 128 / 4) / 256, 256>>>(x);

    dim3 gg(2, N_NODES / 128);
    dim3 ga(2, B_G);
    k_gemm_tc<<<gg, 256, GEMM_SMEM>>>(W1, xw);
    k_agg<true><<<ga, 512, AGG_SMEM>>>(b1, h + 0);
    k_gemm_tc<<<gg, 256, GEMM_SMEM>>>(W2, xw);
    k_agg<true><<<ga, 512, AGG_SMEM>>>(b2, h + 128);
    k_gemm_tc<<<gg, 256, GEMM_SMEM>>>(W3, xw);
    k_agg<false><<<ga, 512, AGG_SMEM>>>(b3, h + 256);

    k_spool<<<B_G, N_PG>>>(Ws, bs);

    k_sgemm_br<<<dim3(4, 2), 256>>>(rd, 768, Wl1, 256, bl1, z1, 256, 768);
    k_sgemm_br<<<dim3(2, 2), 256>>>(z1, 256, Wl2, 128, bl2, z2, 128, 256);
    k_final<<<B_G, 32>>>(Wl3, bl3, (float*)d_out);
}

// round 7
// speedup vs baseline: 1.2992x; 1.0374x over previous
#include <cuda_runtime.h>
#include <cuda_bf16.h>
#include <math.h>
#include <stdint.h>

#define N_NODES 65536
#define B_G     128
#define N_PG    512
#define N_E     1048576
#define K_SEL   256
#define EPG     8192

// ---------------- scratch ----------------
__device__ int   g_deg[N_NODES];
__device__ int   g_off[N_NODES];
__device__ float g_dis[N_NODES];
__device__ int   g_csr[N_E];            // graph-LOCAL source indices
__device__ float g_xw[(size_t)N_NODES * 128];
__device__ float g_h[(size_t)N_NODES * 384];
__device__ __nv_bfloat16 g_ahi[(size_t)N_NODES * 128];   // GEMM A input, hi plane
__device__ __nv_bfloat16 g_alo[(size_t)N_NODES * 128];   // GEMM A input, lo plane
__device__ float g_read[B_G * 768];
__device__ float g_z1[B_G * 256];
__device__ float g_z2[B_G * 128];

// ---------------- fused preprocessing: one block per graph ----------------
__global__ void k_prep(const int* __restrict__ src, const int* __restrict__ dst) {
    __shared__ int degs[N_PG];
    __shared__ int curs[N_PG];
    __shared__ int csr[EPG];
    int g = blockIdx.x, t = threadIdx.x;     // 512 threads
    int nb = g * N_PG, eb = g * EPG;

    degs[t] = 0;
    __syncthreads();
    for (int e = t; e < EPG; e += N_PG) atomicAdd(&degs[dst[eb + e] - nb], 1);
    __syncthreads();

    int d = degs[t];
    curs[t] = d;
    __syncthreads();
    for (int off = 1; off < N_PG; off <<= 1) {
        int v = (t >= off) ? curs[t - off] : 0;
        __syncthreads();
        curs[t] += v;
        __syncthreads();
    }
    int excl = curs[t] - d;
    g_off[nb + t] = eb + excl;
    g_deg[nb + t] = d;
    g_dis[nb + t] = rsqrtf((float)(d + 1));
    curs[t] = excl;
    __syncthreads();

    for (int e = t; e < EPG; e += N_PG) {
        int dl = dst[eb + e] - nb;
        int p = atomicAdd(&curs[dl], 1);
        csr[p] = src[eb + e] - nb;           // local src
    }
    __syncthreads();
    for (int e = t; e < EPG; e += N_PG) g_csr[eb + e] = csr[e];
}

// ---------------- split helpers ----------------
__device__ __forceinline__ void split_pack(float x, float y, uint32_t& hi, uint32_t& lo) {
    __nv_bfloat16 hx = __float2bfloat16_rn(x);
    __nv_bfloat16 hy = __float2bfloat16_rn(y);
    __nv_bfloat16 lx = __float2bfloat16_rn(x - __bfloat162float(hx));
    __nv_bfloat16 ly = __float2bfloat16_rn(y - __bfloat162float(hy));
    hi = ((uint32_t)*(uint16_t*)&hy << 16) | *(uint16_t*)&hx;
    lo = ((uint32_t)*(uint16_t*)&ly << 16) | *(uint16_t*)&lx;
}
__device__ __forceinline__ uint32_t smem_u32(const void* p) {
    return (uint32_t)__cvta_generic_to_shared(p);
}

// ---------------- x -> bf16 hi/lo planes ----------------
__global__ void k_xconv(const float* __restrict__ x) {
    size_t i = (size_t)blockIdx.x * 256 + threadIdx.x;   // float4 index
    float4 v = ((const float4*)x)[i];
    uint32_t h0, l0, h1, l1;
    split_pack(v.x, v.y, h0, l0);
    split_pack(v.z, v.w, h1, l1);
    *(uint2*)((uint16_t*)g_ahi + i * 4) = make_uint2(h0, h1);
    *(uint2*)((uint16_t*)g_alo + i * 4) = make_uint2(l0, l1);
}

// ---------------- tensor-core GEMM (bf16x3): xw[M,128] = planes(A)[M,128] @ W[128,128] ----------------
#define GW_STRIDE 72
#define GA_STRIDE 56
#define GA_PLANE  (128 * GA_STRIDE)
#define GA_BUF    (2 * GA_PLANE)
#define GEMM_SMEM ((2 * 128 * GW_STRIDE + 2 * GA_BUF) * 2)

__global__ void __launch_bounds__(256, 2)
k_gemm_tc(const float* __restrict__ W, float* __restrict__ C) {
    extern __shared__ uint16_t smg[];
    uint16_t* sW = smg;                        // 2 planes x 128 x 72
    uint16_t* sA = smg + 2 * 128 * GW_STRIDE;  // 2 bufs x 2 planes x 128 x 56

    int t = threadIdx.x;
    int cb = blockIdx.x * 64;
    int m0 = blockIdx.y * 128;
    int wid = t >> 5, lane = t & 31;
    int wm = (wid & 3) * 32, wn = (wid >> 2) * 32;

    for (int idx = t; idx < 128 * 16; idx += 256) {
        int k = idx >> 4, cq = (idx & 15) * 4;
        float4 v = *(const float4*)(W + k * 128 + cb + cq);
        uint32_t h0, l0, h1, l1;
        split_pack(v.x, v.y, h0, l0);
        split_pack(v.z, v.w, h1, l1);
        *(uint2*)(sW + k * GW_STRIDE + cq) = make_uint2(h0, h1);
        *(uint2*)(sW + 128 * GW_STRIDE + k * GW_STRIDE + cq) = make_uint2(l0, l1);
    }

    const uint16_t* phi = (const uint16_t*)g_ahi;
    const uint16_t* plo = (const uint16_t*)g_alo;
    uint4 rh[2], rl[2];
#pragma unroll
    for (int i = 0; i < 2; i++) {
        int c = t + i * 256, r = c >> 2, q = c & 3;
        size_t off = (size_t)(m0 + r) * 128 + q * 8;
        rh[i] = *(const uint4*)(phi + off);
        rl[i] = *(const uint4*)(plo + off);
    }

    float acc[2][4][4];
#pragma unroll
    for (int a = 0; a < 2; a++)
#pragma unroll
        for (int b = 0; b < 4; b++)
#pragma unroll
            for (int q = 0; q < 4; q++) acc[a][b][q] = 0.f;

    int a_row0 = wm + (lane & 15);
    int a_coff = (lane >> 4) * 8;
    int b_kr = (lane & 7) + ((lane >> 3) & 1) * 8;
    int b_nc = wn + (lane >> 4) * 8;

    for (int kc = 0; kc < 4; kc++) {
        uint16_t* buf = sA + (kc & 1) * GA_BUF;
#pragma unroll
        for (int i = 0; i < 2; i++) {
            int c = t + i * 256, r = c >> 2, q = c & 3;
            *(uint4*)(buf + r * GA_STRIDE + q * 8) = rh[i];
            *(uint4*)(buf + GA_PLANE + r * GA_STRIDE + q * 8) = rl[i];
        }
        __syncthreads();

        if (kc < 3) {
#pragma unroll
            for (int i = 0; i < 2; i++) {
                int c = t + i * 256, r = c >> 2, q = c & 3;
                size_t off = (size_t)(m0 + r) * 128 + (kc + 1) * 32 + q * 8;
                rh[i] = *(const uint4*)(phi + off);
                rl[i] = *(const uint4*)(plo + off);
            }
        }

#pragma unroll
        for (int ks = 0; ks < 2; ks++) {
            uint32_t ah[2][4], al[2][4];
#pragma unroll
            for (int mi = 0; mi < 2; mi++) {
                uint32_t ad = smem_u32(buf + (a_row0 + mi * 16) * GA_STRIDE + ks * 16 + a_coff);
                asm volatile("ldmatrix.sync.aligned.m8n8.x4.shared.b16 {%0,%1,%2,%3}, [%4];"
                             : "=r"(ah[mi][0]), "=r"(ah[mi][1]), "=r"(ah[mi][2]), "=r"(ah[mi][3])
                             : "r"(ad));
                uint32_t ad2 = smem_u32(buf + GA_PLANE + (a_row0 + mi * 16) * GA_STRIDE + ks * 16 + a_coff);
                asm volatile("ldmatrix.sync.aligned.m8n8.x4.shared.b16 {%0,%1,%2,%3}, [%4];"
                             : "=r"(al[mi][0]), "=r"(al[mi][1]), "=r"(al[mi][2]), "=r"(al[mi][3])
                             : "r"(ad2));
            }
            uint32_t bh[4][2], bl[4][2];
#pragma unroll
            for (int nt = 0; nt < 2; nt++) {
                int krow = ks * 16 + b_kr;
                uint32_t ad = smem_u32(sW + (kc * 32 + krow) * GW_STRIDE + b_nc + nt * 16);
                asm volatile("ldmatrix.sync.aligned.m8n8.x4.trans.shared.b16 {%0,%1,%2,%3}, [%4];"
                             : "=r"(bh[nt * 2][0]), "=r"(bh[nt * 2][1]),
                               "=r"(bh[nt * 2 + 1][0]), "=r"(bh[nt * 2 + 1][1])
                             : "r"(ad));
                uint32_t ad2 = smem_u32(sW + 128 * GW_STRIDE + (kc * 32 + krow) * GW_STRIDE + b_nc + nt * 16);
                asm volatile("ldmatrix.sync.aligned.m8n8.x4.trans.shared.b16 {%0,%1,%2,%3}, [%4];"
                             : "=r"(bl[nt * 2][0]), "=r"(bl[nt * 2][1]),
                               "=r"(bl[nt * 2 + 1][0]), "=r"(bl[nt * 2 + 1][1])
                             : "r"(ad2));
            }
#pragma unroll
            for (int mi = 0; mi < 2; mi++)
#pragma unroll
                for (int nj = 0; nj < 4; nj++) {
                    asm volatile(
                        "mma.sync.aligned.m16n8k16.row.col.f32.bf16.bf16.f32 "
                        "{%0,%1,%2,%3}, {%4,%5,%6,%7}, {%8,%9}, {%0,%1,%2,%3};"
                        : "+f"(acc[mi][nj][0]), "+f"(acc[mi][nj][1]),
                          "+f"(acc[mi][nj][2]), "+f"(acc[mi][nj][3])
                        : "r"(ah[mi][0]), "r"(ah[mi][1]), "r"(ah[mi][2]), "r"(ah[mi][3]),
                          "r"(bh[nj][0]), "r"(bh[nj][1]));
                    asm volatile(
                        "mma.sync.aligned.m16n8k16.row.col.f32.bf16.bf16.f32 "
                        "{%0,%1,%2,%3}, {%4,%5,%6,%7}, {%8,%9}, {%0,%1,%2,%3};"
                        : "+f"(acc[mi][nj][0]), "+f"(acc[mi][nj][1]),
                          "+f"(acc[mi][nj][2]), "+f"(acc[mi][nj][3])
                        : "r"(al[mi][0]), "r"(al[mi][1]), "r"(al[mi][2]), "r"(al[mi][3]),
                          "r"(bh[nj][0]), "r"(bh[nj][1]));
                    asm volatile(
                        "mma.sync.aligned.m16n8k16.row.col.f32.bf16.bf16.f32 "
                        "{%0,%1,%2,%3}, {%4,%5,%6,%7}, {%8,%9}, {%0,%1,%2,%3};"
                        : "+f"(acc[mi][nj][0]), "+f"(acc[mi][nj][1]),
                          "+f"(acc[mi][nj][2]), "+f"(acc[mi][nj][3])
                        : "r"(ah[mi][0]), "r"(ah[mi][1]), "r"(ah[mi][2]), "r"(ah[mi][3]),
                          "r"(bl[nj][0]), "r"(bl[nj][1]));
                }
        }
        __syncthreads();
    }

#pragma unroll
    for (int mi = 0; mi < 2; mi++) {
        int row = m0 + wm + mi * 16 + (lane >> 2);
#pragma unroll
        for (int nj = 0; nj < 4; nj++) {
            int col = cb + wn + nj * 8 + (lane & 3) * 2;
            *(float2*)(C + (size_t)row * 128 + col) = make_float2(acc[mi][nj][0], acc[mi][nj][1]);
            *(float2*)(C + (size_t)(row + 8) * 128 + col) = make_float2(acc[mi][nj][2], acc[mi][nj][3]);
        }
    }
}

// ---------------- aggregate v3: pre-scaled tile, unrolled gather ----------------
// sXD[s][c] = dis[s]*xw[s][c]; out[n] = relu(dn*(sXD[n] + sum_s sXD[s]) + b)
#define AGG_SMEM (512 * 64 * 4 + EPG * 4 + 512 * 4 * 3)
template <bool PLANES>
__global__ void __launch_bounds__(512, 1)
k_agg(const float* __restrict__ bias, float* __restrict__ out) {
    extern __shared__ float sma[];
    float* sX   = sma;                    // [512][64] pre-scaled by dis
    float* sD   = sma + 512 * 64;         // [512]
    int*   sOff = (int*)(sD + 512);       // [512] local
    int*   sDeg = sOff + 512;             // [512]
    int*   sCsr = sDeg + 512;             // [8192]

    int g = blockIdx.y, c0 = blockIdx.x * 64, t = threadIdx.x;
    int nb = g * N_PG, eb = g * EPG;

    sD[t]   = g_dis[nb + t];
    sOff[t] = g_off[nb + t] - eb;
    sDeg[t] = g_deg[nb + t];
    __syncthreads();

    for (int i = t; i < 512 * 16; i += 512) {
        int row = i >> 4, cq = (i & 15) * 4;
        float4 v = *(const float4*)(g_xw + (size_t)(nb + row) * 128 + c0 + cq);
        float s = sD[row];
        v.x *= s; v.y *= s; v.z *= s; v.w *= s;
        *(float4*)&sX[row * 64 + cq] = v;
    }
    for (int e = t * 4; e < EPG; e += 512 * 4)
        *(int4*)&sCsr[e] = *(const int4*)(g_csr + eb + e);
    __syncthreads();

    int w = t >> 5, lane = t & 31;
    const float2* sX2 = (const float2*)sX;
    float2 bb = *(const float2*)(bias + c0 + lane * 2);

    for (int n = w; n < N_PG; n += 16) {
        float2 self = sX2[n * 32 + lane];
        float ax = self.x, ay = self.y;
        int base = sOff[n], d = sDeg[n];
        int j = 0;
        for (; j + 4 <= d; j += 4) {
            int s0 = sCsr[base + j];
            int s1 = sCsr[base + j + 1];
            int s2 = sCsr[base + j + 2];
            int s3 = sCsr[base + j + 3];
            float2 u0 = sX2[s0 * 32 + lane];
            float2 u1 = sX2[s1 * 32 + lane];
            float2 u2 = sX2[s2 * 32 + lane];
            float2 u3 = sX2[s3 * 32 + lane];
            ax += u0.x; ay += u0.y;
            ax += u1.x; ay += u1.y;
            ax += u2.x; ay += u2.y;
            ax += u3.x; ay += u3.y;
        }
        for (; j < d; j++) {
            int s0 = sCsr[base + j];
            float2 u0 = sX2[s0 * 32 + lane];
            ax += u0.x; ay += u0.y;
        }
        float dn = sD[n];
        float ox = fmaxf(dn * ax + bb.x, 0.f);
        float oy = fmaxf(dn * ay + bb.y, 0.f);
        *(float2*)(out + (size_t)(nb + n) * 384 + c0 + lane * 2) = make_float2(ox, oy);
        if (PLANES) {
            size_t po = (size_t)(nb + n) * 128 + c0 + lane * 2;
            __nv_bfloat16 hx = __float2bfloat16_rn(ox);
            __nv_bfloat16 hy = __float2bfloat16_rn(oy);
            uint32_t hp = ((uint32_t)*(uint16_t*)&hy << 16) | *(uint16_t*)&hx;
            __nv_bfloat16 lx = __float2bfloat16_rn(ox - __bfloat162float(hx));
            __nv_bfloat16 ly = __float2bfloat16_rn(oy - __bfloat162float(hy));
            uint32_t lp = ((uint32_t)*(uint16_t*)&ly << 16) | *(uint16_t*)&lx;
            *(uint32_t*)((uint16_t*)g_ahi + po) = hp;
            *(uint32_t*)((uint16_t*)g_alo + po) = lp;
        }
    }
}

// ---------------- fused score GEMV + score aggregate + top-k + gated readout ----------------
__global__ void k_spool(const float* __restrict__ Wsc, const float* __restrict__ bs) {
    __shared__ float ws[384];
    __shared__ float spre[N_PG];      // pre-scaled by dis
    __shared__ float dss[N_PG];
    __shared__ float scr[N_PG];
    __shared__ unsigned long long key[N_PG];
    __shared__ int sel[K_SEL];
    __shared__ float gate[K_SEL];

    int g = blockIdx.x, t = threadIdx.x;    // 512 threads
    int nb = g * N_PG;
    if (t < 384) ws[t] = Wsc[t];
    dss[t] = g_dis[nb + t];
    __syncthreads();

    int w = t >> 5, lane = t & 31;
    for (int i = 0; i < 32; i++) {
        int n = i * 16 + w;
        const float* h = g_h + (size_t)(nb + n) * 384;
        float acc = 0.f;
#pragma unroll
        for (int c = lane * 4; c < 384; c += 128) {
            float4 hv = *(const float4*)(h + c);
            float4 wv = *(const float4*)(ws + c);
            acc += hv.x * wv.x + hv.y * wv.y + hv.z * wv.z + hv.w * wv.w;
        }
#pragma unroll
        for (int o = 16; o; o >>= 1) acc += __shfl_xor_sync(0xffffffffu, acc, o);
        if (lane == 0) spre[n] = acc * dss[n];    // pre-scale
    }
    __syncthreads();

    float dn = dss[t];
    float sc = spre[t];
    int base = g_off[nb + t], d = g_deg[nb + t];
    int j = 0;
    for (; j + 4 <= d; j += 4) {
        int s0 = g_csr[base + j], s1 = g_csr[base + j + 1];
        int s2 = g_csr[base + j + 2], s3 = g_csr[base + j + 3];
        sc += spre[s0] + spre[s1] + spre[s2] + spre[s3];
    }
    for (; j < d; j++) sc += spre[g_csr[base + j]];
    sc = dn * sc + bs[0];
    scr[t] = sc;

    unsigned u = __float_as_uint(sc);
    u = (u & 0x80000000u) ? ~u : (u ^ 0x80000000u);
    u = ~u;                                  // descending order
    key[t] = ((unsigned long long)u << 32) | (unsigned)t;
    __syncthreads();

    for (int k = 2; k <= N_PG; k <<= 1) {
        for (int j2 = k >> 1; j2 > 0; j2 >>= 1) {
            int ixj = t ^ j2;
            if (ixj > t) {
                unsigned long long a = key[t], b = key[ixj];
                bool up = ((t & k) == 0);
                if ((a > b) == up) { key[t] = b; key[ixj] = a; }
            }
            __syncthreads();
        }
    }

    if (t < K_SEL) {
        int idx = (int)(key[t] & 0xffffffffu);
        sel[t] = idx;
        gate[t] = tanhf(scr[idx]);
    }
    __syncthreads();

    if (t < 384) {
        float vmax = __int_as_float(0xff800000);
        float vsum = 0.f;
        const float* hb = g_h + (size_t)nb * 384;
        for (int i = 0; i < K_SEL; i++) {
            float v = hb[(size_t)sel[i] * 384 + t] * gate[i];
            vmax = fmaxf(vmax, v);
            vsum += v;
        }
        g_read[g * 768 + t] = vmax;
        g_read[g * 768 + 384 + t] = vsum * (1.0f / K_SEL);
    }
}

// ---------------- small SGEMM (MLP head): C = A(MxK)*B(KxN), bias+relu ----------------
__global__ void k_sgemm_br(const float* __restrict__ A, int lda,
                           const float* __restrict__ B, int ldb,
                           const float* __restrict__ bias,
                           float* __restrict__ C, int ldc, int Kdim) {
    __shared__ float As[16][68];
    __shared__ float Bs[16][68];
    int tid = threadIdx.x;
    int tx = tid & 15, ty = tid >> 4;
    int arow = tid >> 2, acol = (tid & 3) * 4;
    int brow = tid >> 4, bcol = (tid & 15) * 4;
    int row0 = blockIdx.y * 64, col0 = blockIdx.x * 64;
    const float* Aptr = A + (size_t)(row0 + arow) * lda + acol;
    const float* Bptr = B + (size_t)brow * ldb + col0 + bcol;
    float acc[4][4];
#pragma unroll
    for (int i = 0; i < 4; i++)
#pragma unroll
        for (int j = 0; j < 4; j++) acc[i][j] = 0.f;
    for (int k0 = 0; k0 < Kdim; k0 += 16) {
        float4 a = *(const float4*)(Aptr + k0);
        float4 b = *(const float4*)(Bptr + (size_t)k0 * ldb);
        As[acol + 0][arow] = a.x; As[acol + 1][arow] = a.y;
        As[acol + 2][arow] = a.z; As[acol + 3][arow] = a.w;
        *(float4*)&Bs[brow][bcol] = b;
        __syncthreads();
#pragma unroll
        for (int k = 0; k < 16; k++) {
            float ar[4], br[4];
            *(float4*)ar = *(const float4*)&As[k][ty * 4];
            *(float4*)br = *(const float4*)&Bs[k][tx * 4];
#pragma unroll
            for (int i = 0; i < 4; i++)
#pragma unroll
                for (int j = 0; j < 4; j++) acc[i][j] += ar[i] * br[j];
        }
        __syncthreads();
    }
#pragma unroll
    for (int i = 0; i < 4; i++)
#pragma unroll
        for (int j = 0; j < 4; j++) {
            int col = col0 + tx * 4 + j;
            C[(size_t)(row0 + ty * 4 + i) * ldc + col] =
                fmaxf(acc[i][j] + bias[col], 0.f);
        }
}

// ---------------- final layer + log_softmax ----------------
__global__ void k_final(const float* __restrict__ Wl3, const float* __restrict__ bl3,
                        float* __restrict__ out) {
    int r = blockIdx.x;
    int lane = threadIdx.x;
    float4 zv = *(const float4*)(g_z2 + r * 128 + lane * 4);
    float logits[10];
#pragma unroll
    for (int o = 0; o < 10; o++) {
        int k = lane * 4;
        float p = zv.x * Wl3[(k + 0) * 10 + o] + zv.y * Wl3[(k + 1) * 10 + o] +
                  zv.z * Wl3[(k + 2) * 10 + o] + zv.w * Wl3[(k + 3) * 10 + o];
#pragma unroll
        for (int s = 16; s; s >>= 1) p += __shfl_xor_sync(0xffffffffu, p, s);
        logits[o] = p + bl3[o];
    }
    if (lane == 0) {
        float m = logits[0];
#pragma unroll
        for (int o = 1; o < 10; o++) m = fmaxf(m, logits[o]);
        float se = 0.f;
#pragma unroll
        for (int o = 0; o < 10; o++) se += expf(logits[o] - m);
        float lse = m + logf(se);
#pragma unroll
        for (int o = 0; o < 10; o++) out[r * 10 + o] = logits[o] - lse;
    }
}

// ---------------- launcher ----------------
extern "C" void kernel_launch(void* const* d_in, const int* in_sizes, int n_in,
                              void* d_out, int out_size) {
    const float* x   = (const float*)d_in[0];
    const int*   ei  = (const int*)d_in[1];
    const float* W1  = (const float*)d_in[2];
    const float* b1  = (const float*)d_in[3];
    const float* W2  = (const float*)d_in[4];
    const float* b2  = (const float*)d_in[5];
    const float* W3  = (const float*)d_in[6];
    const float* b3  = (const float*)d_in[7];
    const float* Ws  = (const float*)d_in[8];
    const float* bs  = (const float*)d_in[9];
    const float* Wl1 = (const float*)d_in[10];
    const float* bl1 = (const float*)d_in[11];
    const float* Wl2 = (const float*)d_in[12];
    const float* bl2 = (const float*)d_in[13];
    const float* Wl3 = (const float*)d_in[14];
    const float* bl3 = (const float*)d_in[15];

    const int* src = ei;
    const int* dst = ei + N_E;

    static int attr_done = 0;
    if (!attr_done) {
        cudaFuncSetAttribute(k_gemm_tc, cudaFuncAttributeMaxDynamicSharedMemorySize, GEMM_SMEM);
        cudaFuncSetAttribute(k_agg<true>, cudaFuncAttributeMaxDynamicSharedMemorySize, AGG_SMEM);
        cudaFuncSetAttribute(k_agg<false>, cudaFuncAttributeMaxDynamicSharedMemorySize, AGG_SMEM);
        attr_done = 1;
    }

    void* p;
    cudaGetSymbolAddress(&p, g_xw);   float* xw = (float*)p;
    cudaGetSymbolAddress(&p, g_h);    float* h  = (float*)p;
    cudaGetSymbolAddress(&p, g_read); float* rd = (float*)p;
    cudaGetSymbolAddress(&p, g_z1);   float* z1 = (float*)p;
    cudaGetSymbolAddress(&p, g_z2);   float* z2 = (float*)p;

    k_prep<<<B_G, N_PG>>>(src, dst);
    k_xconv<<<(N_NODES * 128 / 4) / 256, 256>>>(x);

    dim3 gg(2, N_NODES / 128);
    dim3 ga(2, B_G);
    k_gemm_tc<<<gg, 256, GEMM_SMEM>>>(W1, xw);
    k_agg<true><<<ga, 512, AGG_SMEM>>>(b1, h + 0);
    k_gemm_tc<<<gg, 256, GEMM_SMEM>>>(W2, xw);
    k_agg<true><<<ga, 512, AGG_SMEM>>>(b2, h + 128);
    k_gemm_tc<<<gg, 256, GEMM_SMEM>>>(W3, xw);
    k_agg<false><<<ga, 512, AGG_SMEM>>>(b3, h + 256);

    k_spool<<<B_G, N_PG>>>(Ws, bs);

    k_sgemm_br<<<dim3(4, 2), 256>>>(rd, 768, Wl1, 256, bl1, z1, 256, 768);
    k_sgemm_br<<<dim3(2, 2), 256>>>(z1, 256, Wl2, 128, bl2, z2, 128, 256);
    k_final<<<B_G, 32>>>(Wl3, bl3, (float*)d_out);
}